// round 1
// baseline (speedup 1.0000x reference)
#include <cuda_runtime.h>
#include <cstdint>

#define Fdim 16
#define Sdim 512
#define Odim 32
#define Bdim 256
#define NCH  16   // number of shift-chunks
#define SC   32   // shifts per chunk (Sdim / NCH)
#define BT   16   // batch rows per block
#define NBT  16   // Bdim / BT

// Partial maxima scratch: [chunk][b][f][o] = 16*256*16*32 floats = 8 MB (L2-resident)
__device__ float g_partial[NCH * Bdim * Fdim * Odim];

// ---------------------------------------------------------------------------
// Kernel 1: per (batch-tile, shift-chunk) block computes
//   partial[ch][b][f][o] = max_{s in chunk} x[b,s,f] * W[s,f,o]
// ---------------------------------------------------------------------------
__global__ __launch_bounds__(512, 2) void k1_partial(const float* __restrict__ x,
                                                     const float* __restrict__ W) {
    extern __shared__ float sm[];
    float* xs = sm;                    // [BT][SC][Fdim]  = 8192 floats (32 KB)
    float* ws = sm + BT * SC * Fdim;   // [SC][Fdim][Odim]= 16384 floats (64 KB)

    const int tid   = threadIdx.x;
    const int btile = blockIdx.x;      // 0..NBT-1
    const int ch    = blockIdx.y;      // 0..NCH-1

    // ---- stage x tile: 16 rows x 512 contiguous floats each, float4 copy ----
    #pragma unroll
    for (int it = 0; it < 4; ++it) {
        int idx = tid + it * 512;          // 0..2047 float4s
        int b   = idx >> 7;                // 128 float4 per row
        int t   = idx & 127;
        float4 v = *(const float4*)(x + (size_t)(btile * BT + b) * (Sdim * Fdim)
                                      + ch * SC * Fdim + t * 4);
        *(float4*)(xs + b * (SC * Fdim) + t * 4) = v;   // conflict-free
    }

    // ---- stage W tile: contiguous 64 KB float4 copy ----
    {
        const float4* wsrc = (const float4*)(W + (size_t)ch * SC * Fdim * Odim);
        #pragma unroll
        for (int it = 0; it < 8; ++it) {
            int idx = tid + it * 512;      // 0..4095 float4s
            ((float4*)ws)[idx] = wsrc[idx];
        }
    }
    __syncthreads();

    // thread handles (o, f0..f0+3, b0..b0+3)
    const int o  = tid & 31;
    const int f0 = ((tid >> 5) & 3) * 4;
    const int b0 = (tid >> 7) * 4;

    const float NEG = __int_as_float(0xff800000);   // -inf
    float acc[4][4];
    #pragma unroll
    for (int i = 0; i < 4; ++i)
        #pragma unroll
        for (int j = 0; j < 4; ++j) acc[i][j] = NEG;

    #pragma unroll 4
    for (int s = 0; s < SC; ++s) {
        // W reads: stride-1 across warp (o in lanes) -> conflict-free
        const float w0 = ws[(s * Fdim + f0 + 0) * Odim + o];
        const float w1 = ws[(s * Fdim + f0 + 1) * Odim + o];
        const float w2 = ws[(s * Fdim + f0 + 2) * Odim + o];
        const float w3 = ws[(s * Fdim + f0 + 3) * Odim + o];
        #pragma unroll
        for (int i = 0; i < 4; ++i) {
            // uniform address across warp -> LDS.128 broadcast (1 wavefront)
            const float4 xv = *(const float4*)(xs + ((b0 + i) * SC + s) * Fdim + f0);
            acc[i][0] = fmaxf(acc[i][0], xv.x * w0);
            acc[i][1] = fmaxf(acc[i][1], xv.y * w1);
            acc[i][2] = fmaxf(acc[i][2], xv.z * w2);
            acc[i][3] = fmaxf(acc[i][3], xv.w * w3);
        }
    }

    // ---- store partial maxima (coalesced over o) ----
    #pragma unroll
    for (int i = 0; i < 4; ++i) {
        const int bglob = btile * BT + b0 + i;
        #pragma unroll
        for (int j = 0; j < 4; ++j) {
            g_partial[((ch * Bdim + bglob) * Fdim + (f0 + j)) * Odim + o] = acc[i][j];
        }
    }
}

// ---------------------------------------------------------------------------
// Kernel 2: out[b,o] = relu( bias[o] + sum_f max_ch partial[ch][b][f][o] )
// One block per batch row; thread = (f, o).
// ---------------------------------------------------------------------------
__global__ __launch_bounds__(512) void k2_reduce(const float* __restrict__ bias,
                                                 float* __restrict__ out) {
    const int b   = blockIdx.x;
    const int tid = threadIdx.x;
    const int o   = tid & 31;
    const int f   = tid >> 5;

    const float NEG = __int_as_float(0xff800000);
    float m = NEG;
    #pragma unroll
    for (int ch = 0; ch < NCH; ++ch)
        m = fmaxf(m, g_partial[((ch * Bdim + b) * Fdim + f) * Odim + o]);

    __shared__ float red[Fdim][Odim + 1];   // +1 pad: conflict-free column read
    red[f][o] = m;
    __syncthreads();

    if (tid < 32) {
        float sum = bias[tid];
        #pragma unroll
        for (int ff = 0; ff < Fdim; ++ff) sum += red[ff][tid];
        out[b * Odim + tid] = fmaxf(sum, 0.0f);
    }
}

// ---------------------------------------------------------------------------
extern "C" void kernel_launch(void* const* d_in, const int* in_sizes, int n_in,
                              void* d_out, int out_size) {
    const float* x    = (const float*)d_in[0];   // [256, 8192]
    const float* W    = (const float*)d_in[1];   // [8192, 32]
    const float* bias = (const float*)d_in[2];   // [32]
    float* out        = (float*)d_out;           // [256, 32]

    // 96 KB dynamic smem (> 48 KB default) — idempotent, capture-safe
    cudaFuncSetAttribute(k1_partial, cudaFuncAttributeMaxDynamicSharedMemorySize,
                         96 * 1024);

    dim3 g1(NBT, NCH);
    k1_partial<<<g1, 512, 96 * 1024>>>(x, W);
    k2_reduce<<<Bdim, 512>>>(bias, out);
}